// round 16
// baseline (speedup 1.0000x reference)
#include <cuda_runtime.h>
#include <cuda_fp16.h>
#include <math.h>
#include <cstdint>

#define NN 200000
#define NE 800000
#define NG 8192
#define HD 200
#define NLAYERS 5
#define TSTEPS 2
#define LDP 224

#define WSLOT (1040 * 256)
#define NSLOTS 14

// ------------------------- scratch (static device globals) -------------------------
__device__ __half d_hh[(size_t)NN * LDP];
__device__ __half d_hl[(size_t)NN * LDP];
__device__ __half d_agg[(size_t)NN * LDP];
__device__ __half d_hv[(size_t)NN * LDP];
__device__ __half d_ctx[NG * LDP];
__device__ __half d_gp[NG * LDP];
__device__ __half d_nah[(size_t)NN * 96];
__device__ __half d_nal[(size_t)NN * 96];
__device__ __half d_ea[(size_t)NE * 32];
__device__ __half d_e16[(size_t)NE * HD];
// fp32 state
__device__ float d_g[NG * HD];
__device__ float d_gi[NG * 600];
__device__ float d_ghb[NG * 600];
__device__ float d_t1[NG * 1024];
__device__ float d_z[NN];
__device__ float d_aw[NN];
__device__ float d_zh[2 * NN];
__device__ float d_zg[NG];
__device__ float d_zmax[NG];
__device__ float d_zden[NG];
// CSR
__device__ int d_cnt[NN];
__device__ int d_rowptr[NN + 1];
__device__ int d_fill[NN];
__device__ int d_adjsrc[NE];
__device__ int d_eperm[NE];
__device__ int d_gcnt[NG];
__device__ int d_gptr[NG + 1];
__device__ int d_bsums[1024];
// weights pre-transposed + fp16 hi/lo split: [slot][1040 n-rows][256 k]
__device__ __half d_wall_h[NSLOTS * WSLOT];
__device__ __half d_wall_l[NSLOTS * WSLOT];

// ------------------------- helpers -------------------------
__device__ __forceinline__ uint32_t smem_u32(const void* p) {
    uint32_t a;
    asm("{ .reg .u64 t; cvta.to.shared.u64 t, %1; cvt.u32.u64 %0, t; }" : "=r"(a) : "l"(p));
    return a;
}

__device__ __forceinline__ void mma16816h(float* c, unsigned a0, unsigned a1,
                                          unsigned a2, unsigned a3,
                                          unsigned b0, unsigned b1) {
    asm volatile(
        "mma.sync.aligned.m16n8k16.row.col.f32.f16.f16.f32 "
        "{%0,%1,%2,%3}, {%4,%5,%6,%7}, {%8,%9}, {%0,%1,%2,%3};\n"
        : "+f"(c[0]), "+f"(c[1]), "+f"(c[2]), "+f"(c[3])
        : "r"(a0), "r"(a1), "r"(a2), "r"(a3), "r"(b0), "r"(b1));
}

#define LDSM_X4(r, a) \
    asm volatile("ldmatrix.sync.aligned.m8n8.x4.shared.b16 {%0,%1,%2,%3}, [%4];" \
                 : "=r"((r)[0]), "=r"((r)[1]), "=r"((r)[2]), "=r"((r)[3]) : "r"(a))

#define CP16(dst, src) \
    asm volatile("cp.async.ca.shared.global [%0], [%1], 16;" :: "r"(dst), "l"(src))
#define CPCOMMIT() asm volatile("cp.async.commit_group;" ::: "memory")
#define CPWAIT0() asm volatile("cp.async.wait_group 0;" ::: "memory")
#define CPWAIT1() asm volatile("cp.async.wait_group 1;" ::: "memory")
#define CPWAIT2() asm volatile("cp.async.wait_group 2;" ::: "memory")

__device__ __forceinline__ unsigned packh2(__half a, __half b) {
    return ((unsigned)__half_as_ushort(b) << 16) | (unsigned)__half_as_ushort(a);
}

__device__ __forceinline__ void splith(float v0, float v1, unsigned& hi, unsigned& lo) {
    __half h0 = __float2half_rn(v0), h1 = __float2half_rn(v1);
    hi = packh2(h0, h1);
    lo = packh2(__float2half_rn(v0 - __half2float(h0)),
                __float2half_rn(v1 - __half2float(h1)));
}

// ------------------------- one-shot weight transpose + fp16 split -------------------------
struct WSlotDesc {
    const float* W;
    int K, NCOL, ldw;
};
struct WTable {
    WSlotDesc s[NSLOTS];
};

__global__ void wconv_all(WTable T, __half* __restrict__ wh, __half* __restrict__ wl) {
    long gid = (long)blockIdx.x * blockDim.x + threadIdx.x;
    if (gid >= (long)NSLOTS * WSLOT) return;
    int slot = (int)(gid / WSLOT);
    int rem = (int)(gid - (long)slot * WSLOT);
    int n = rem >> 8;
    int k = rem & 255;
    WSlotDesc d = T.s[slot];
    float v = (n < d.NCOL && k < d.K) ? d.W[(long)k * d.ldw + n] : 0.f;
    __half h = __float2half_rn(v);
    wh[gid] = h;
    wl[gid] = __float2half_rn(v - __half2float(h));
}

// ------------------------- input feature split -------------------------
__global__ void split2_kernel(const float* __restrict__ X, int M, int K, int lda,
                              __half* __restrict__ oh, __half* __restrict__ ol) {
    long gid = (long)blockIdx.x * blockDim.x + threadIdx.x;
    if (gid >= (long)M * lda) return;
    int r = (int)(gid / lda);
    int k = (int)(gid - (long)r * lda);
    float v = (k < K) ? X[(long)r * K + k] : 0.f;
    __half h = __float2half_rn(v);
    oh[gid] = h;
    ol[gid] = __float2half_rn(v - __half2float(h));
}

__global__ void split1_kernel(const float* __restrict__ X, int M, int K, int lda,
                              __half* __restrict__ oh) {
    long gid = (long)blockIdx.x * blockDim.x + threadIdx.x;
    if (gid >= (long)M * lda) return;
    int r = (int)(gid / lda);
    int k = (int)(gid - (long)r * lda);
    float v = (k < K) ? X[(long)r * K + k] : 0.f;
    oh[gid] = __float2half_rn(v);
}

__global__ void zpad_kernel(__half* __restrict__ ph, __half* __restrict__ pl, int M) {
    long gid = (long)blockIdx.x * blockDim.x + threadIdx.x;
    if (gid >= (long)M * (LDP - HD)) return;
    int r = (int)(gid / (LDP - HD));
    int c = HD + (int)(gid - (long)r * (LDP - HD));
    ph[(long)r * LDP + c] = __ushort_as_half(0);
    if (pl) pl[(long)r * LDP + c] = __ushort_as_half(0);
}

// ------------------------- shared epilogue -------------------------
__device__ __forceinline__ void epi_store(
    float v0, float v1, int gr, int gc, int mode,
    const float* __restrict__ bias, const float* __restrict__ ls,
    float* __restrict__ Cf, int ldc,
    __half* __restrict__ Poh, __half* __restrict__ Pol,
    __half* __restrict__ P1, int s1, const int* __restrict__ rowmap) {
    v0 += bias ? bias[gc] : 0.f;
    v1 += bias ? bias[gc + 1] : 0.f;
    if (mode == 1) {
        size_t po = (size_t)gr * LDP + gc;
        float o0 = __half2float(Poh[po]) + __half2float(Pol[po]);
        float o1 = __half2float(Poh[po + 1]) + __half2float(Pol[po + 1]);
        v0 = fmaxf(v0, 0.f) * ls[gc] + o0;
        v1 = fmaxf(v1, 0.f) * ls[gc + 1] + o1;
    }
    if (Cf) {
        float* crow = Cf + (size_t)gr * ldc;
        crow[gc] = v0;
        crow[gc + 1] = v1;
    }
    if (Poh) {
        unsigned hi, lo;
        splith(v0, v1, hi, lo);
        *(unsigned*)(Poh + (size_t)gr * LDP + gc) = hi;
        *(unsigned*)(Pol + (size_t)gr * LDP + gc) = lo;
    }
    if (P1) {
        int orow = rowmap ? rowmap[gr] : gr;
        *(__half2*)(P1 + (size_t)orow * s1 + gc) = __floats2half2_rn(v0, v1);
    }
}

// ------------------------- fp16 split GEMM: 128x128 tile, 3-stage cp.async -------------------------
// (used for small-M GEMMs where grid parallelism matters)
template <int AP>
__global__ __launch_bounds__(256, 2) void mma_gemmT(
    const __half* __restrict__ Ah, const __half* __restrict__ Al, int lda,
    const __half* __restrict__ Bh, const __half* __restrict__ Bl,
    const float* __restrict__ bias,
    float* __restrict__ Cf, int ldc,
    __half* __restrict__ Poh, __half* __restrict__ Pol,
    __half* __restrict__ P1, int s1, const int* __restrict__ rowmap,
    int M, int NCOL, int mode, const float* __restrict__ ls) {
    extern __shared__ char sm[];
    uint4* sAq = (uint4*)sm;
    uint4* sBq = (uint4*)(sm + AP * 24576);
    uint32_t smbA = smem_u32(sm);
    uint32_t smbB = smbA + AP * 24576;

    int tid = threadIdx.x;
    int wid = tid >> 5;
    int lane = tid & 31;
    int warp_m = wid & 3;
    int warp_n = wid >> 2;
    int row0 = blockIdx.x * 128;
    int col0 = blockIdx.y * 128;

    float acc[2][8][4];
#pragma unroll
    for (int s = 0; s < 2; s++)
#pragma unroll
        for (int nt = 0; nt < 8; nt++)
#pragma unroll
            for (int i = 0; i < 4; i++) acc[s][nt][i] = 0.f;

    int nch = lda >> 5;

    auto issue_loads = [&](int c, int stage) {
        int k0 = c << 5;
#pragma unroll
        for (int p = tid; p < AP * 512; p += 256) {
            int plane = (AP == 2) ? (p >> 9) : 0;
            int rem = p & 511;
            int r = rem >> 2;
            int u = rem & 3;
            int rr = row0 + r;
            if (rr >= M) rr = M - 1;
            const __half* srcA = (plane ? Al : Ah) + (size_t)rr * lda + k0 + u * 8;
            uint32_t dstA = smbA + (uint32_t)(stage * (AP * 512) + plane * 512 + r * 4 +
                                              (u ^ ((r >> 1) & 3))) * 16u;
            CP16(dstA, srcA);
        }
#pragma unroll
        for (int p = tid; p < 1024; p += 256) {
            int plane = p >> 9;
            int rem = p & 511;
            int r = rem >> 2;
            int u = rem & 3;
            const __half* srcB = (plane ? Bl : Bh) + (size_t)(col0 + r) * 256 + k0 + u * 8;
            uint32_t dstB = smbB + (uint32_t)(stage * 1024 + plane * 512 + r * 4 +
                                              (u ^ ((r >> 1) & 3))) * 16u;
            CP16(dstB, srcB);
        }
    };

    issue_loads(0, 0);
    CPCOMMIT();
    if (nch > 1) {
        issue_loads(1, 1);
        CPCOMMIT();
    }

    for (int c = 0; c < nch; c++) {
        __syncthreads();
        if (c + 2 < nch) {
            issue_loads(c + 2, (c + 2) % 3);
            CPCOMMIT();
            CPWAIT2();
        } else if (c + 1 < nch) {
            CPWAIT1();
        } else {
            CPWAIT0();
        }
        __syncthreads();

        int abase = (c % 3) * (AP * 512);
        int bbase = (c % 3) * 1024;
#pragma unroll
        for (int kh = 0; kh < 2; kh++) {
            unsigned ah[2][4], al[2][4];
#pragma unroll
            for (int s = 0; s < 2; s++) {
                int r = warp_m * 32 + s * 16 + (lane & 15);
                int u = kh * 2 + (lane >> 4);
                int up = u ^ ((r >> 1) & 3);
                LDSM_X4(ah[s], smem_u32(&sAq[abase + r * 4 + up]));
                if (AP == 2) LDSM_X4(al[s], smem_u32(&sAq[abase + 512 + r * 4 + up]));
            }
            int nb = warp_n * 64;
#pragma unroll
            for (int i = 0; i < 4; i++) {
                int r = nb + i * 16 + (lane & 7) + ((lane >> 4) << 3);
                int u = kh * 2 + ((lane >> 3) & 1);
                int up = u ^ ((r >> 1) & 3);
                unsigned bh[4], bl[4];
                LDSM_X4(bh, smem_u32(&sBq[bbase + r * 4 + up]));
                LDSM_X4(bl, smem_u32(&sBq[bbase + 512 + r * 4 + up]));
#pragma unroll
                for (int s = 0; s < 2; s++) {
                    mma16816h(acc[s][2 * i], ah[s][0], ah[s][1], ah[s][2], ah[s][3], bh[0], bh[1]);
                    mma16816h(acc[s][2 * i], ah[s][0], ah[s][1], ah[s][2], ah[s][3], bl[0], bl[1]);
                    if (AP == 2)
                        mma16816h(acc[s][2 * i], al[s][0], al[s][1], al[s][2], al[s][3], bh[0], bh[1]);
                    mma16816h(acc[s][2 * i + 1], ah[s][0], ah[s][1], ah[s][2], ah[s][3], bh[2], bh[3]);
                    mma16816h(acc[s][2 * i + 1], ah[s][0], ah[s][1], ah[s][2], ah[s][3], bl[2], bl[3]);
                    if (AP == 2)
                        mma16816h(acc[s][2 * i + 1], al[s][0], al[s][1], al[s][2], al[s][3], bh[2], bh[3]);
                }
            }
        }
    }

#pragma unroll
    for (int s = 0; s < 2; s++) {
        int grb = row0 + warp_m * 32 + s * 16 + (lane >> 2);
#pragma unroll
        for (int nt = 0; nt < 8; nt++) {
            int gc = col0 + warp_n * 64 + nt * 8 + (lane & 3) * 2;
#pragma unroll
            for (int half = 0; half < 2; half++) {
                int gr = grb + half * 8;
                if (gr >= M || gc >= NCOL) continue;
                epi_store(acc[s][nt][half * 2], acc[s][nt][half * 2 + 1], gr, gc, mode,
                          bias, ls, Cf, ldc, Poh, Pol, P1, s1, rowmap);
            }
        }
    }
}

// ------------------------- A-resident multi-col-tile GEMM (large M) -------------------------
// grid.y = 1. A row-block loaded to smem ONCE; loop over col tiles x k-chunks with the
// proven 3-stage/2-sync B pipeline (flat iteration space).
template <int AP>
__global__ __launch_bounds__(256, 2) void mma_gemmR(
    const __half* __restrict__ Ah, const __half* __restrict__ Al, int lda,
    const __half* __restrict__ Bh, const __half* __restrict__ Bl,
    const float* __restrict__ bias,
    float* __restrict__ Cf, int ldc,
    __half* __restrict__ Poh, __half* __restrict__ Pol,
    __half* __restrict__ P1, int s1, const int* __restrict__ rowmap,
    int M, int NCOL, int mode, const float* __restrict__ ls) {
    extern __shared__ char sm[];
    int nch = lda >> 5;
    uint4* sAq = (uint4*)sm;
    uint4* sBq = (uint4*)(sm + (size_t)AP * nch * 8192);
    uint32_t smbA = smem_u32(sm);
    uint32_t smbB = smbA + AP * nch * 8192;

    int tid = threadIdx.x;
    int wid = tid >> 5;
    int lane = tid & 31;
    int warp_m = wid & 3;
    int warp_n = wid >> 2;
    int row0 = blockIdx.x * 128;
    int NCT = (NCOL + 127) >> 7;
    int total = NCT * nch;

    float acc[2][8][4];
#pragma unroll
    for (int s = 0; s < 2; s++)
#pragma unroll
        for (int nt = 0; nt < 8; nt++)
#pragma unroll
            for (int i = 0; i < 4; i++) acc[s][nt][i] = 0.f;

    // ---- issue ALL A chunks (resident) ----
    for (int c = 0; c < nch; c++) {
        for (int p = tid; p < AP * 512; p += 256) {
            int plane = (AP == 2) ? (p >> 9) : 0;
            int rem = p & 511;
            int r = rem >> 2;
            int u = rem & 3;
            int rr = row0 + r;
            if (rr >= M) rr = M - 1;
            const __half* srcA = (plane ? Al : Ah) + (size_t)rr * lda + c * 32 + u * 8;
            uint32_t dstA = smbA + (uint32_t)((c * AP + plane) * 512 + r * 4 +
                                              (u ^ ((r >> 1) & 3))) * 16u;
            CP16(dstA, srcA);
        }
    }

    auto issueB = [&](int iter, int stage) {
        int ct = iter / nch;
        int c = iter - ct * nch;
#pragma unroll
        for (int p = tid; p < 1024; p += 256) {
            int plane = p >> 9;
            int rem = p & 511;
            int r = rem >> 2;
            int u = rem & 3;
            const __half* srcB = (plane ? Bl : Bh) + (size_t)(ct * 128 + r) * 256 +
                                 c * 32 + u * 8;
            uint32_t dstB = smbB + (uint32_t)(stage * 1024 + plane * 512 + r * 4 +
                                              (u ^ ((r >> 1) & 3))) * 16u;
            CP16(dstB, srcB);
        }
    };

    issueB(0, 0);
    CPCOMMIT();   // group: A + B0
    if (total > 1) {
        issueB(1, 1);
        CPCOMMIT();
    }

    for (int iter = 0; iter < total; iter++) {
        __syncthreads();
        if (iter + 2 < total) {
            issueB(iter + 2, (iter + 2) % 3);
            CPCOMMIT();
            CPWAIT2();
        } else if (iter + 1 < total) {
            CPWAIT1();
        } else {
            CPWAIT0();
        }
        __syncthreads();

        int ct = iter / nch;
        int c = iter - ct * nch;
        int abase = c * AP * 512;
        int bbase = (iter % 3) * 1024;
#pragma unroll
        for (int kh = 0; kh < 2; kh++) {
            unsigned ah[2][4], al[2][4];
#pragma unroll
            for (int s = 0; s < 2; s++) {
                int r = warp_m * 32 + s * 16 + (lane & 15);
                int u = kh * 2 + (lane >> 4);
                int up = u ^ ((r >> 1) & 3);
                LDSM_X4(ah[s], smem_u32(&sAq[abase + r * 4 + up]));
                if (AP == 2) LDSM_X4(al[s], smem_u32(&sAq[abase + 512 + r * 4 + up]));
            }
            int nb = warp_n * 64;
#pragma unroll
            for (int i = 0; i < 4; i++) {
                int r = nb + i * 16 + (lane & 7) + ((lane >> 4) << 3);
                int u = kh * 2 + ((lane >> 3) & 1);
                int up = u ^ ((r >> 1) & 3);
                unsigned bh[4], bl[4];
                LDSM_X4(bh, smem_u32(&sBq[bbase + r * 4 + up]));
                LDSM_X4(bl, smem_u32(&sBq[bbase + 512 + r * 4 + up]));
#pragma unroll
                for (int s = 0; s < 2; s++) {
                    mma16816h(acc[s][2 * i], ah[s][0], ah[s][1], ah[s][2], ah[s][3], bh[0], bh[1]);
                    mma16816h(acc[s][2 * i], ah[s][0], ah[s][1], ah[s][2], ah[s][3], bl[0], bl[1]);
                    if (AP == 2)
                        mma16816h(acc[s][2 * i], al[s][0], al[s][1], al[s][2], al[s][3], bh[0], bh[1]);
                    mma16816h(acc[s][2 * i + 1], ah[s][0], ah[s][1], ah[s][2], ah[s][3], bh[2], bh[3]);
                    mma16816h(acc[s][2 * i + 1], ah[s][0], ah[s][1], ah[s][2], ah[s][3], bl[2], bl[3]);
                    if (AP == 2)
                        mma16816h(acc[s][2 * i + 1], al[s][0], al[s][1], al[s][2], al[s][3], bh[2], bh[3]);
                }
            }
        }

        // ---- end of col tile: epilogue + reset acc (regs/global only, pipeline-safe) ----
        if (c == nch - 1) {
            int col0 = ct * 128;
#pragma unroll
            for (int s = 0; s < 2; s++) {
                int grb = row0 + warp_m * 32 + s * 16 + (lane >> 2);
#pragma unroll
                for (int nt = 0; nt < 8; nt++) {
                    int gc = col0 + warp_n * 64 + nt * 8 + (lane & 3) * 2;
#pragma unroll
                    for (int half = 0; half < 2; half++) {
                        int gr = grb + half * 8;
                        if (gr >= M || gc >= NCOL) continue;
                        epi_store(acc[s][nt][half * 2], acc[s][nt][half * 2 + 1], gr, gc,
                                  mode, bias, ls, Cf, ldc, Poh, Pol, P1, s1, rowmap);
                    }
                }
            }
#pragma unroll
            for (int s = 0; s < 2; s++)
#pragma unroll
                for (int nt = 0; nt < 8; nt++)
#pragma unroll
                    for (int i = 0; i < 4; i++) acc[s][nt][i] = 0.f;
        }
    }
}

// ------------------------- small utility kernels -------------------------
__global__ void zero_int(int* p, int n) {
    int gid = blockIdx.x * blockDim.x + threadIdx.x;
    if (gid < n) p[gid] = 0;
}

__global__ void hist_kernel(const int* __restrict__ idx, int* __restrict__ cnt, int n) {
    int gid = blockIdx.x * blockDim.x + threadIdx.x;
    if (gid < n) atomicAdd(&cnt[idx[gid]], 1);
}

__global__ void scan1_kernel(const int* __restrict__ in, int* __restrict__ outp1,
                             int* __restrict__ bsums, int n) {
    __shared__ int sh[1024];
    int t = threadIdx.x;
    long base = (long)blockIdx.x * 8192 + (long)t * 8;
    int v[8];
    int run = 0;
#pragma unroll
    for (int i = 0; i < 8; i++) {
        long idx = base + i;
        int x = (idx < n) ? in[idx] : 0;
        run += x;
        v[i] = run;
    }
    sh[t] = run;
    __syncthreads();
    int total = run;
    for (int off = 1; off < 1024; off <<= 1) {
        int y = (t >= off) ? sh[t - off] : 0;
        __syncthreads();
        sh[t] += y;
        __syncthreads();
    }
    int excl = sh[t] - total;
#pragma unroll
    for (int i = 0; i < 8; i++) {
        long idx = base + i;
        if (idx < n) outp1[idx + 1] = v[i] + excl;
    }
    if (t == 1023) bsums[blockIdx.x] = sh[1023];
    if (blockIdx.x == 0 && t == 0) outp1[0] = 0;
}

__global__ void scan2_kernel(int* bsums, int nb) {
    __shared__ int sh[1024];
    int t = threadIdx.x;
    int v = (t < nb) ? bsums[t] : 0;
    sh[t] = v;
    __syncthreads();
    for (int off = 1; off < 1024; off <<= 1) {
        int y = (t >= off) ? sh[t - off] : 0;
        __syncthreads();
        sh[t] += y;
        __syncthreads();
    }
    if (t < nb) bsums[t] = sh[t] - v;  // exclusive
}

__global__ void scan3_kernel(int* outp1, const int* __restrict__ bsums, int n) {
    int gid = blockIdx.x * blockDim.x + threadIdx.x;
    if (gid < n) outp1[gid + 1] += bsums[gid >> 13];
}

__global__ void copy_int(const int* __restrict__ a, int* __restrict__ b, int n) {
    int gid = blockIdx.x * blockDim.x + threadIdx.x;
    if (gid < n) b[gid] = a[gid];
}

__global__ void fill_adj2_kernel(const int* __restrict__ src, const int* __restrict__ dst,
                                 int* __restrict__ fill, int* __restrict__ adjsrc,
                                 int* __restrict__ eperm, int n) {
    int gid = blockIdx.x * blockDim.x + threadIdx.x;
    if (gid < n) {
        int d = dst[gid];
        int pos = atomicAdd(&fill[d], 1);
        adjsrc[pos] = src[gid];
        eperm[gid] = pos;
    }
}

// ------------------------- message passing (no max-shift: |m| is O(1)) -------------------------
__global__ void msg16_kernel(const __half2* __restrict__ h2, const __half2* __restrict__ e2,
                             const int* __restrict__ rowptr, const int* __restrict__ adjsrc,
                             __half* __restrict__ agg) {
    long gid = (long)blockIdx.x * blockDim.x + threadIdx.x;
    if (gid >= (long)NN * 112) return;
    int v = (int)(gid / 112);
    int f = (int)(gid - (long)v * 112);
    int c0 = 2 * f;
    if (c0 >= HD) {
        *(unsigned*)(agg + (long)v * LDP + c0) = 0u;
        return;
    }
    int b = rowptr[v], en = rowptr[v + 1];
    float d0 = 0.f, d1 = 0.f, a0 = 0.f, a1 = 0.f;
    for (int p = b; p < en; p++) {
        int sidx = adjsrc[p];
        float2 hh = __half22float2(h2[(long)sidx * 112 + f]);
        float2 ee = __half22float2(e2[(long)p * 100 + f]);
        float m0 = hh.x + ee.x;
        float m1 = hh.y + ee.y;
        float p0 = __expf(m0);
        float p1 = __expf(m1);
        d0 += p0;
        a0 = fmaf(p0, m0, a0);
        d1 += p1;
        a1 = fmaf(p1, m1, a1);
    }
    float r0 = (d0 > 0.f) ? a0 / d0 : 0.f;
    float r1 = (d1 > 0.f) ? a1 / d1 : 0.f;
    *(__half2*)(agg + (long)v * LDP + c0) = __floats2half2_rn(r0, r1);
}

// ------------------------- graph readout kernels -------------------------
__global__ void gsum_kernel(const __half* __restrict__ hh,
                            const int* __restrict__ gptr, float* __restrict__ g,
                            __half* __restrict__ gp) {
    int gid = blockIdx.x * blockDim.x + threadIdx.x;
    if (gid >= NG * LDP) return;
    int gg = gid / LDP;
    int f = gid - gg * LDP;
    if (f >= HD) {
        gp[gid] = __ushort_as_half(0);
        return;
    }
    int b = gptr[gg], e = gptr[gg + 1];
    float s = 0.f;
    for (int n = b; n < e; n++) s += __half2float(hh[(long)n * LDP + f]);
    g[gg * HD + f] = s;
    gp[gid] = __float2half_rn(s);
}

__global__ void zpre_kernel(const __half* __restrict__ hh,
                            const float* __restrict__ logit_W, float* __restrict__ zh) {
    int warp = (blockIdx.x * blockDim.x + threadIdx.x) >> 5;
    int lane = threadIdx.x & 31;
    if (warp >= NN) return;
    const __half* rh = hh + (long)warp * LDP;
    float s0 = 0.f, s1 = 0.f;
    for (int f = lane; f < HD; f += 32) {
        float hv = __half2float(rh[f]);
        s0 += hv * logit_W[HD + f];
        s1 += hv * logit_W[2 * HD + HD + f];
    }
#pragma unroll
    for (int o = 16; o; o >>= 1) {
        s0 += __shfl_xor_sync(0xffffffffu, s0, o);
        s1 += __shfl_xor_sync(0xffffffffu, s1, o);
    }
    if (lane == 0) {
        zh[warp] = s0;
        zh[NN + warp] = s1;
    }
}

__global__ void zgr_kernel(const float* __restrict__ g, const float* __restrict__ lwg,
                           float* __restrict__ zg) {
    int warp = (blockIdx.x * blockDim.x + threadIdx.x) >> 5;
    int lane = threadIdx.x & 31;
    if (warp >= NG) return;
    const float* grow = g + (long)warp * HD;
    float s = 0.f;
    for (int f = lane; f < HD; f += 32) s += fmaxf(grow[f], 0.f) * lwg[f];
#pragma unroll
    for (int o = 16; o; o >>= 1) s += __shfl_xor_sync(0xffffffffu, s, o);
    if (lane == 0) zg[warp] = s;
}

__global__ void zcomb_kernel(const float* __restrict__ zg, const int* __restrict__ n2g,
                             const float* __restrict__ zh, const float* __restrict__ lb,
                             float* __restrict__ z) {
    int gid = blockIdx.x * blockDim.x + threadIdx.x;
    if (gid >= NN) return;
    float v = zg[n2g[gid]] + zh[gid] + lb[0];
    z[gid] = (v > 0.f) ? v : 0.01f * v;  // leaky_relu
}

__global__ void attn_kernel(const float* __restrict__ z, const int* __restrict__ gptr,
                            float* __restrict__ zmax, float* __restrict__ zden) {
    int warp = (blockIdx.x * blockDim.x + threadIdx.x) >> 5;
    int lane = threadIdx.x & 31;
    if (warp >= NG) return;
    int b = gptr[warp], e = gptr[warp + 1];
    float mx = -3.4e38f;
    for (int i = b + lane; i < e; i += 32) mx = fmaxf(mx, z[i]);
#pragma unroll
    for (int o = 16; o; o >>= 1) mx = fmaxf(mx, __shfl_xor_sync(0xffffffffu, mx, o));
    float s = 0.f;
    for (int i = b + lane; i < e; i += 32) s += __expf(z[i] - mx);
#pragma unroll
    for (int o = 16; o; o >>= 1) s += __shfl_xor_sync(0xffffffffu, s, o);
    if (lane == 0) {
        zmax[warp] = mx;
        zden[warp] = s;
    }
}

__global__ void aw_kernel(const float* __restrict__ z, const int* __restrict__ n2g,
                          const float* __restrict__ zmax, const float* __restrict__ zden,
                          float* __restrict__ aw) {
    int gid = blockIdx.x * blockDim.x + threadIdx.x;
    if (gid >= NN) return;
    int gg = n2g[gid];
    aw[gid] = __expf(z[gid] - zmax[gg]) / zden[gg];
}

__global__ void ctx_kernel(const __half* __restrict__ hv, const float* __restrict__ aw,
                           const int* __restrict__ gptr, __half* __restrict__ ctx) {
    int gid = blockIdx.x * blockDim.x + threadIdx.x;
    if (gid >= NG * LDP) return;
    int gg = gid / LDP;
    int f = gid - gg * LDP;
    if (f >= HD) {
        ctx[gid] = __ushort_as_half(0);
        return;
    }
    int b = gptr[gg], e = gptr[gg + 1];
    float s = 0.f;
    for (int n = b; n < e; n++)
        s = fmaf(__half2float(hv[(long)n * LDP + f]), aw[n], s);
    float v = (s > 0.f) ? s : (__expf(s) - 1.f);  // elu
    ctx[gid] = __float2half_rn(v);
}

__global__ void gru_kernel(const float* __restrict__ gi, const float* __restrict__ gh,
                           float* __restrict__ g, __half* __restrict__ gp) {
    int gid = blockIdx.x * blockDim.x + threadIdx.x;
    if (gid >= NG * HD) return;
    int gg = gid / HD;
    int f = gid - gg * HD;
    const float* gib = gi + gg * 600;
    const float* ghb2 = gh + gg * 600;
    float r = 1.f / (1.f + __expf(-(gib[f] + ghb2[f])));
    float u = 1.f / (1.f + __expf(-(gib[200 + f] + ghb2[200 + f])));
    float nn = tanhf(gib[400 + f] + r * ghb2[400 + f]);
    float v = (1.f - u) * nn + u * g[gid];
    g[gid] = v;
    gp[gg * LDP + f] = __float2half_rn(v);
}

__global__ void out2_kernel(const float* __restrict__ tmp, const float* __restrict__ w2,
                            const float* __restrict__ b2, float* __restrict__ out) {
    int warp = (blockIdx.x * blockDim.x + threadIdx.x) >> 5;
    int lane = threadIdx.x & 31;
    if (warp >= NG) return;
    float s = 0.f;
    const float* row = tmp + (long)warp * 1024;
    for (int c = lane; c < 1024; c += 32) s += fmaxf(row[c], 0.f) * w2[c];
#pragma unroll
    for (int o = 16; o; o >>= 1) s += __shfl_xor_sync(0xffffffffu, s, o);
    if (lane == 0) out[warp] = s + b2[0];
}

// ------------------------- launch -------------------------
static __half *g_pwh, *g_pwl;

static void launch_gemm(int slot, const __half* Ah, const __half* Al, int lda,
                        const float* bias, float* Cf, int ldc,
                        __half* Poh, __half* Pol, __half* P1, int s1,
                        const int* rowmap, int M, int NCOL, int mode, const float* ls) {
    const __half* Bh = g_pwh + (size_t)slot * WSLOT;
    const __half* Bl = g_pwl + (size_t)slot * WSLOT;
    int ap = Al ? 2 : 1;
    if (M >= 100000) {
        // A-resident variant, grid.y = 1
        int nch = lda >> 5;
        int smem = ap * nch * 8192 + 49152;
        dim3 grid((M + 127) / 128, 1);
        if (ap == 2)
            mma_gemmR<2><<<grid, 256, smem>>>(Ah, Al, lda, Bh, Bl, bias, Cf, ldc, Poh,
                                              Pol, P1, s1, rowmap, M, NCOL, mode, ls);
        else
            mma_gemmR<1><<<grid, 256, smem>>>(Ah, nullptr, lda, Bh, Bl, bias, Cf, ldc,
                                              Poh, Pol, P1, s1, rowmap, M, NCOL, mode, ls);
    } else {
        dim3 grid((M + 127) / 128, (NCOL + 127) / 128);
        if (ap == 2)
            mma_gemmT<2><<<grid, 256, 98304>>>(Ah, Al, lda, Bh, Bl, bias, Cf, ldc, Poh,
                                               Pol, P1, s1, rowmap, M, NCOL, mode, ls);
        else
            mma_gemmT<1><<<grid, 256, 73728>>>(Ah, nullptr, lda, Bh, Bl, bias, Cf, ldc,
                                               Poh, Pol, P1, s1, rowmap, M, NCOL, mode, ls);
    }
}

extern "C" void kernel_launch(void* const* d_in, const int* in_sizes, int n_in,
                              void* d_out, int out_size) {
    const float* node_feats = (const float*)d_in[0];
    const float* edge_feats = (const float*)d_in[1];
    const int* src = (const int*)d_in[2];
    const int* dst = (const int*)d_in[3];
    const int* n2g = (const int*)d_in[4];
    const float* atom_W = (const float*)d_in[5];
    const float* atom_b = (const float*)d_in[6];
    const float* bond_W = (const float*)d_in[7];
    const float* bond_b = (const float*)d_in[8];
    const float* mlp_W = (const float*)d_in[9];
    const float* mlp_b = (const float*)d_in[10];
    const float* ls = (const float*)d_in[11];
    const float* logit_W = (const float*)d_in[12];
    const float* logit_b = (const float*)d_in[13];
    const float* proj_W = (const float*)d_in[14];
    const float* proj_b = (const float*)d_in[15];
    const float* gru_Wih = (const float*)d_in[16];
    const float* gru_Whh = (const float*)d_in[17];
    const float* gru_bih = (const float*)d_in[18];
    const float* gru_bhh = (const float*)d_in[19];
    const float* out1_W = (const float*)d_in[20];
    const float* out1_b = (const float*)d_in[21];
    const float* out2_W = (const float*)d_in[22];
    const float* out2_b = (const float*)d_in[23];
    float* out = (float*)d_out;

    cudaFuncSetAttribute(mma_gemmT<2>, cudaFuncAttributeMaxDynamicSharedMemorySize, 98304);
    cudaFuncSetAttribute(mma_gemmT<1>, cudaFuncAttributeMaxDynamicSharedMemorySize, 73728);
    cudaFuncSetAttribute(mma_gemmR<2>, cudaFuncAttributeMaxDynamicSharedMemorySize, 106496);
    cudaFuncSetAttribute(mma_gemmR<1>, cudaFuncAttributeMaxDynamicSharedMemorySize, 106496);

    __half *phh, *phl, *pagg, *phv, *pctx, *pgp, *pnah, *pnal, *pea, *pe16;
    float *pg, *pgi, *pghb, *pt1, *pz, *paw, *pzh, *pzg, *pzmax, *pzden;
    int *pcnt, *prow, *pfill, *pgcnt, *pgptr, *pbs, *padjsrc, *peperm;
    cudaGetSymbolAddress((void**)&phh, d_hh);
    cudaGetSymbolAddress((void**)&phl, d_hl);
    cudaGetSymbolAddress((void**)&pagg, d_agg);
    cudaGetSymbolAddress((void**)&phv, d_hv);
    cudaGetSymbolAddress((void**)&pctx, d_ctx);
    cudaGetSymbolAddress((void**)&pgp, d_gp);
    cudaGetSymbolAddress((void**)&pnah, d_nah);
    cudaGetSymbolAddress((void**)&pnal, d_nal);
    cudaGetSymbolAddress((void**)&pea, d_ea);
    cudaGetSymbolAddress((void**)&pe16, d_e16);
    cudaGetSymbolAddress((void**)&pg, d_g);
    cudaGetSymbolAddress((void**)&pgi, d_gi);
    cudaGetSymbolAddress((void**)&pghb, d_ghb);
    cudaGetSymbolAddress((void**)&pt1, d_t1);
    cudaGetSymbolAddress((void**)&pz, d_z);
    cudaGetSymbolAddress((void**)&paw, d_aw);
    cudaGetSymbolAddress((void**)&pzh, d_zh);
    cudaGetSymbolAddress((void**)&pzg, d_zg);
    cudaGetSymbolAddress((void**)&pzmax, d_zmax);
    cudaGetSymbolAddress((void**)&pzden, d_zden);
    cudaGetSymbolAddress((void**)&pcnt, d_cnt);
    cudaGetSymbolAddress((void**)&prow, d_rowptr);
    cudaGetSymbolAddress((void**)&pfill, d_fill);
    cudaGetSymbolAddress((void**)&pgcnt, d_gcnt);
    cudaGetSymbolAddress((void**)&pgptr, d_gptr);
    cudaGetSymbolAddress((void**)&pbs, d_bsums);
    cudaGetSymbolAddress((void**)&padjsrc, d_adjsrc);
    cudaGetSymbolAddress((void**)&peperm, d_eperm);
    cudaGetSymbolAddress((void**)&g_pwh, d_wall_h);
    cudaGetSymbolAddress((void**)&g_pwl, d_wall_l);

    // ---- slot table ----
    WTable T;
    T.s[0] = {atom_W, 74, HD, HD};
    T.s[1] = {bond_W, 12, HD, HD};
    for (int i = 0; i < NLAYERS; i++) T.s[2 + i] = {mlp_W + (size_t)i * HD * HD, HD, HD, HD};
    for (int t = 0; t < TSTEPS; t++) {
        T.s[7 + t] = {proj_W + (size_t)t * HD * HD, HD, HD, HD};
        T.s[9 + t] = {gru_Wih + (size_t)t * HD * 600, HD, 600, 600};
        T.s[11 + t] = {gru_Whh + (size_t)t * HD * 600, HD, 600, 600};
    }
    T.s[13] = {out1_W, HD, 1024, 1024};

    // prep + node encoder early (ncu capture = launch 4)
    wconv_all<<<(NSLOTS * WSLOT + 255) / 256, 256>>>(T, g_pwh, g_pwl);
    split2_kernel<<<(int)(((long)NN * 96 + 255) / 256), 256>>>(node_feats, NN, 74, 96, pnah, pnal);
    split1_kernel<<<(int)(((long)NE * 32 + 255) / 256), 256>>>(edge_feats, NE, 12, 32, pea);
    launch_gemm(0, pnah, pnal, 96, atom_b, nullptr, 0, phh, phl, nullptr, 0, nullptr,
                NN, HD, 0, nullptr);
    zpad_kernel<<<(int)(((long)NN * (LDP - HD) + 255) / 256), 256>>>(phh, phl, NN);

    // ---- CSR by dst ----
    zero_int<<<(NN + 255) / 256, 256>>>(pcnt, NN);
    hist_kernel<<<(NE + 255) / 256, 256>>>(dst, pcnt, NE);
    int nb1 = (NN + 8191) / 8192;
    scan1_kernel<<<nb1, 1024>>>(pcnt, prow, pbs, NN);
    scan2_kernel<<<1, 1024>>>(pbs, nb1);
    scan3_kernel<<<(NN + 255) / 256, 256>>>(prow, pbs, NN);
    copy_int<<<(NN + 255) / 256, 256>>>(prow, pfill, NN);
    fill_adj2_kernel<<<(NE + 255) / 256, 256>>>(src, dst, pfill, padjsrc, peperm, NE);

    // edge encoder: single-plane A, writes e16 directly in CSR order via eperm
    launch_gemm(1, pea, nullptr, 32, bond_b, nullptr, 0, nullptr, nullptr, pe16, HD,
                peperm, NE, HD, 0, nullptr);

    // ---- graph offsets ----
    zero_int<<<(NG + 255) / 256, 256>>>(pgcnt, NG);
    hist_kernel<<<(NN + 255) / 256, 256>>>(n2g, pgcnt, NN);
    scan1_kernel<<<1, 1024>>>(pgcnt, pgptr, pbs, NG);
    scan2_kernel<<<1, 1024>>>(pbs, 1);
    scan3_kernel<<<(NG + 255) / 256, 256>>>(pgptr, pbs, NG);

    // ---- message passing layers ----
    long nthr = (long)NN * 112;
    int mblocks = (int)((nthr + 255) / 256);
    for (int i = 0; i < NLAYERS; i++) {
        msg16_kernel<<<mblocks, 256>>>((const __half2*)phh, (const __half2*)pe16,
                                       prow, padjsrc, pagg);
        launch_gemm(2 + i, pagg, nullptr, LDP, mlp_b + i * HD, nullptr, 0, phh, phl,
                    nullptr, 0, nullptr, NN, HD, 1, ls + i * HD);
    }

    // ---- readout ----
    gsum_kernel<<<(NG * LDP + 255) / 256, 256>>>(phh, pgptr, pg, pgp);
    zpre_kernel<<<(NN * 32 + 255) / 256, 256>>>(phh, logit_W, pzh);
    for (int t = 0; t < TSTEPS; t++) {
        zgr_kernel<<<(NG * 32 + 255) / 256, 256>>>(pg, logit_W + t * 2 * HD, pzg);
        zcomb_kernel<<<(NN + 255) / 256, 256>>>(pzg, n2g, pzh + t * NN, logit_b + t, pz);
        attn_kernel<<<(NG * 32 + 255) / 256, 256>>>(pz, pgptr, pzmax, pzden);
        aw_kernel<<<(NN + 255) / 256, 256>>>(pz, n2g, pzmax, pzden, paw);
        // proj: single-plane A (hh only)
        launch_gemm(7 + t, phh, nullptr, LDP, proj_b + t * HD, nullptr, 0, nullptr,
                    nullptr, phv, LDP, nullptr, NN, HD, 0, nullptr);
        ctx_kernel<<<(NG * LDP + 255) / 256, 256>>>(phv, paw, pgptr, pctx);
        launch_gemm(9 + t, pctx, nullptr, LDP, gru_bih + t * 600, pgi, 600, nullptr,
                    nullptr, nullptr, 0, nullptr, NG, 600, 0, nullptr);
        launch_gemm(11 + t, pgp, nullptr, LDP, gru_bhh + t * 600, pghb, 600, nullptr,
                    nullptr, nullptr, 0, nullptr, NG, 600, 0, nullptr);
        gru_kernel<<<(NG * HD + 255) / 256, 256>>>(pgi, pghb, pg, pgp);
    }

    launch_gemm(13, pgp, nullptr, LDP, out1_b, pt1, 1024, nullptr, nullptr, nullptr, 0,
                nullptr, NG, 1024, 0, nullptr);
    out2_kernel<<<(NG * 32 + 255) / 256, 256>>>(pt1, out2_W, out2_b, out);
}

// round 17
// speedup vs baseline: 1.3306x; 1.3306x over previous
#include <cuda_runtime.h>
#include <cuda_fp16.h>
#include <math.h>
#include <cstdint>

#define NN 200000
#define NE 800000
#define NG 8192
#define HD 200
#define NLAYERS 5
#define TSTEPS 2
#define LDP 224

#define WSLOT (1040 * 256)
#define NSLOTS 14

// ------------------------- scratch (static device globals) -------------------------
__device__ __half d_hh[(size_t)NN * LDP];
__device__ __half d_hl[(size_t)NN * LDP];
__device__ __half d_agg[(size_t)NN * LDP];
__device__ __half d_hv[(size_t)NN * LDP];
__device__ __half d_hv2[(size_t)NN * LDP];
__device__ __half d_ctx[NG * LDP];
__device__ __half d_gp[NG * LDP];
__device__ __half d_nah[(size_t)NN * 96];
__device__ __half d_nal[(size_t)NN * 96];
__device__ __half d_ea[(size_t)NE * 32];
__device__ __half d_e16[(size_t)NE * HD];
// fp32 state
__device__ float d_g[NG * HD];
__device__ float d_gi[NG * 600];
__device__ float d_ghb[NG * 600];
__device__ float d_t1[NG * 1024];
__device__ float d_z[NN];
__device__ float d_aw[NN];
__device__ float d_zh[2 * NN];
__device__ float d_zg[NG];
__device__ float d_zmax[NG];
__device__ float d_zden[NG];
// CSR
__device__ int d_cnt[NN];
__device__ int d_rowptr[NN + 1];
__device__ int d_fill[NN];
__device__ int d_adjsrc[NE];
__device__ int d_eperm[NE];
__device__ int d_gcnt[NG];
__device__ int d_gptr[NG + 1];
__device__ int d_bsums[1024];
// weights pre-transposed + fp16 hi/lo split: [slot][1040 n-rows][256 k]
__device__ __half d_wall_h[NSLOTS * WSLOT];
__device__ __half d_wall_l[NSLOTS * WSLOT];

// ------------------------- helpers -------------------------
__device__ __forceinline__ uint32_t smem_u32(const void* p) {
    uint32_t a;
    asm("{ .reg .u64 t; cvta.to.shared.u64 t, %1; cvt.u32.u64 %0, t; }" : "=r"(a) : "l"(p));
    return a;
}

__device__ __forceinline__ void mma16816h(float* c, unsigned a0, unsigned a1,
                                          unsigned a2, unsigned a3,
                                          unsigned b0, unsigned b1) {
    asm volatile(
        "mma.sync.aligned.m16n8k16.row.col.f32.f16.f16.f32 "
        "{%0,%1,%2,%3}, {%4,%5,%6,%7}, {%8,%9}, {%0,%1,%2,%3};\n"
        : "+f"(c[0]), "+f"(c[1]), "+f"(c[2]), "+f"(c[3])
        : "r"(a0), "r"(a1), "r"(a2), "r"(a3), "r"(b0), "r"(b1));
}

#define LDSM_X4(r, a) \
    asm volatile("ldmatrix.sync.aligned.m8n8.x4.shared.b16 {%0,%1,%2,%3}, [%4];" \
                 : "=r"((r)[0]), "=r"((r)[1]), "=r"((r)[2]), "=r"((r)[3]) : "r"(a))

#define CP16(dst, src) \
    asm volatile("cp.async.ca.shared.global [%0], [%1], 16;" :: "r"(dst), "l"(src))
#define CPCOMMIT() asm volatile("cp.async.commit_group;" ::: "memory")
#define CPWAIT0() asm volatile("cp.async.wait_group 0;" ::: "memory")
#define CPWAIT1() asm volatile("cp.async.wait_group 1;" ::: "memory")
#define CPWAIT2() asm volatile("cp.async.wait_group 2;" ::: "memory")

__device__ __forceinline__ unsigned packh2(__half a, __half b) {
    return ((unsigned)__half_as_ushort(b) << 16) | (unsigned)__half_as_ushort(a);
}

__device__ __forceinline__ void splith(float v0, float v1, unsigned& hi, unsigned& lo) {
    __half h0 = __float2half_rn(v0), h1 = __float2half_rn(v1);
    hi = packh2(h0, h1);
    lo = packh2(__float2half_rn(v0 - __half2float(h0)),
                __float2half_rn(v1 - __half2float(h1)));
}

// ------------------------- one-shot weight transpose + fp16 split -------------------------
struct WSlotDesc {
    const float* W;
    int K, NCOL, ldw;
};
struct WTable {
    WSlotDesc s[NSLOTS];
};

__global__ void wconv_all(WTable T, __half* __restrict__ wh, __half* __restrict__ wl) {
    long gid = (long)blockIdx.x * blockDim.x + threadIdx.x;
    if (gid >= (long)NSLOTS * WSLOT) return;
    int slot = (int)(gid / WSLOT);
    int rem = (int)(gid - (long)slot * WSLOT);
    int n = rem >> 8;
    int k = rem & 255;
    WSlotDesc d = T.s[slot];
    float v = (n < d.NCOL && k < d.K) ? d.W[(long)k * d.ldw + n] : 0.f;
    __half h = __float2half_rn(v);
    wh[gid] = h;
    wl[gid] = __float2half_rn(v - __half2float(h));
}

// ------------------------- input feature split -------------------------
__global__ void split2_kernel(const float* __restrict__ X, int M, int K, int lda,
                              __half* __restrict__ oh, __half* __restrict__ ol) {
    long gid = (long)blockIdx.x * blockDim.x + threadIdx.x;
    if (gid >= (long)M * lda) return;
    int r = (int)(gid / lda);
    int k = (int)(gid - (long)r * lda);
    float v = (k < K) ? X[(long)r * K + k] : 0.f;
    __half h = __float2half_rn(v);
    oh[gid] = h;
    ol[gid] = __float2half_rn(v - __half2float(h));
}

__global__ void split1_kernel(const float* __restrict__ X, int M, int K, int lda,
                              __half* __restrict__ oh) {
    long gid = (long)blockIdx.x * blockDim.x + threadIdx.x;
    if (gid >= (long)M * lda) return;
    int r = (int)(gid / lda);
    int k = (int)(gid - (long)r * lda);
    float v = (k < K) ? X[(long)r * K + k] : 0.f;
    oh[gid] = __float2half_rn(v);
}

__global__ void zpad_kernel(__half* __restrict__ ph, __half* __restrict__ pl, int M) {
    long gid = (long)blockIdx.x * blockDim.x + threadIdx.x;
    if (gid >= (long)M * (LDP - HD)) return;
    int r = (int)(gid / (LDP - HD));
    int c = HD + (int)(gid - (long)r * (LDP - HD));
    ph[(long)r * LDP + c] = __ushort_as_half(0);
    if (pl) pl[(long)r * LDP + c] = __ushort_as_half(0);
}

// ------------------------- shared epilogue -------------------------
__device__ __forceinline__ void epi_store(
    float v0, float v1, int gr, int gc, int mode,
    const float* __restrict__ bias, const float* __restrict__ ls,
    float* __restrict__ Cf, int ldc,
    __half* __restrict__ Poh, __half* __restrict__ Pol,
    __half* __restrict__ P1, int s1, const int* __restrict__ rowmap) {
    v0 += bias ? bias[gc] : 0.f;
    v1 += bias ? bias[gc + 1] : 0.f;
    if (mode == 1) {
        size_t po = (size_t)gr * LDP + gc;
        float o0 = __half2float(Poh[po]) + __half2float(Pol[po]);
        float o1 = __half2float(Poh[po + 1]) + __half2float(Pol[po + 1]);
        v0 = fmaxf(v0, 0.f) * ls[gc] + o0;
        v1 = fmaxf(v1, 0.f) * ls[gc + 1] + o1;
    }
    if (Cf) {
        float* crow = Cf + (size_t)gr * ldc;
        crow[gc] = v0;
        crow[gc + 1] = v1;
    }
    if (Poh) {
        unsigned hi, lo;
        splith(v0, v1, hi, lo);
        *(unsigned*)(Poh + (size_t)gr * LDP + gc) = hi;
        *(unsigned*)(Pol + (size_t)gr * LDP + gc) = lo;
    }
    if (P1) {
        int orow = rowmap ? rowmap[gr] : gr;
        *(__half2*)(P1 + (size_t)orow * s1 + gc) = __floats2half2_rn(v0, v1);
    }
}

// ------------------------- GEMM core body (proven 3-stage / 2-sync) -------------------------
template <int AP>
__device__ __forceinline__ void gemm_body(
    const __half* __restrict__ Ah, const __half* __restrict__ Al, int lda,
    const __half* __restrict__ Bh, const __half* __restrict__ Bl,
    const float* __restrict__ bias,
    float* __restrict__ Cf, int ldc,
    __half* __restrict__ Poh, __half* __restrict__ Pol,
    __half* __restrict__ P1, int s1, const int* __restrict__ rowmap,
    int M, int NCOL, int mode, const float* __restrict__ ls) {
    extern __shared__ char sm[];
    uint4* sAq = (uint4*)sm;
    uint4* sBq = (uint4*)(sm + AP * 24576);
    uint32_t smbA = smem_u32(sm);
    uint32_t smbB = smbA + AP * 24576;

    int tid = threadIdx.x;
    int wid = tid >> 5;
    int lane = tid & 31;
    int warp_m = wid & 3;
    int warp_n = wid >> 2;
    int row0 = blockIdx.x * 128;
    int col0 = blockIdx.y * 128;

    float acc[2][8][4];
#pragma unroll
    for (int s = 0; s < 2; s++)
#pragma unroll
        for (int nt = 0; nt < 8; nt++)
#pragma unroll
            for (int i = 0; i < 4; i++) acc[s][nt][i] = 0.f;

    int nch = lda >> 5;

    auto issue_loads = [&](int c, int stage) {
        int k0 = c << 5;
#pragma unroll
        for (int p = tid; p < AP * 512; p += 256) {
            int plane = (AP == 2) ? (p >> 9) : 0;
            int rem = p & 511;
            int r = rem >> 2;
            int u = rem & 3;
            int rr = row0 + r;
            if (rr >= M) rr = M - 1;
            const __half* srcA = (plane ? Al : Ah) + (size_t)rr * lda + k0 + u * 8;
            uint32_t dstA = smbA + (uint32_t)(stage * (AP * 512) + plane * 512 + r * 4 +
                                              (u ^ ((r >> 1) & 3))) * 16u;
            CP16(dstA, srcA);
        }
#pragma unroll
        for (int p = tid; p < 1024; p += 256) {
            int plane = p >> 9;
            int rem = p & 511;
            int r = rem >> 2;
            int u = rem & 3;
            const __half* srcB = (plane ? Bl : Bh) + (size_t)(col0 + r) * 256 + k0 + u * 8;
            uint32_t dstB = smbB + (uint32_t)(stage * 1024 + plane * 512 + r * 4 +
                                              (u ^ ((r >> 1) & 3))) * 16u;
            CP16(dstB, srcB);
        }
    };

    issue_loads(0, 0);
    CPCOMMIT();
    if (nch > 1) {
        issue_loads(1, 1);
        CPCOMMIT();
    }

    for (int c = 0; c < nch; c++) {
        __syncthreads();
        if (c + 2 < nch) {
            issue_loads(c + 2, (c + 2) % 3);
            CPCOMMIT();
            CPWAIT2();
        } else if (c + 1 < nch) {
            CPWAIT1();
        } else {
            CPWAIT0();
        }
        __syncthreads();

        int abase = (c % 3) * (AP * 512);
        int bbase = (c % 3) * 1024;
#pragma unroll
        for (int kh = 0; kh < 2; kh++) {
            unsigned ah[2][4], al[2][4];
#pragma unroll
            for (int s = 0; s < 2; s++) {
                int r = warp_m * 32 + s * 16 + (lane & 15);
                int u = kh * 2 + (lane >> 4);
                int up = u ^ ((r >> 1) & 3);
                LDSM_X4(ah[s], smem_u32(&sAq[abase + r * 4 + up]));
                if (AP == 2) LDSM_X4(al[s], smem_u32(&sAq[abase + 512 + r * 4 + up]));
            }
            int nb = warp_n * 64;
#pragma unroll
            for (int i = 0; i < 4; i++) {
                int r = nb + i * 16 + (lane & 7) + ((lane >> 4) << 3);
                int u = kh * 2 + ((lane >> 3) & 1);
                int up = u ^ ((r >> 1) & 3);
                unsigned bh[4], bl[4];
                LDSM_X4(bh, smem_u32(&sBq[bbase + r * 4 + up]));
                LDSM_X4(bl, smem_u32(&sBq[bbase + 512 + r * 4 + up]));
#pragma unroll
                for (int s = 0; s < 2; s++) {
                    mma16816h(acc[s][2 * i], ah[s][0], ah[s][1], ah[s][2], ah[s][3], bh[0], bh[1]);
                    mma16816h(acc[s][2 * i], ah[s][0], ah[s][1], ah[s][2], ah[s][3], bl[0], bl[1]);
                    if (AP == 2)
                        mma16816h(acc[s][2 * i], al[s][0], al[s][1], al[s][2], al[s][3], bh[0], bh[1]);
                    mma16816h(acc[s][2 * i + 1], ah[s][0], ah[s][1], ah[s][2], ah[s][3], bh[2], bh[3]);
                    mma16816h(acc[s][2 * i + 1], ah[s][0], ah[s][1], ah[s][2], ah[s][3], bl[2], bl[3]);
                    if (AP == 2)
                        mma16816h(acc[s][2 * i + 1], al[s][0], al[s][1], al[s][2], al[s][3], bh[2], bh[3]);
                }
            }
        }
    }

#pragma unroll
    for (int s = 0; s < 2; s++) {
        int grb = row0 + warp_m * 32 + s * 16 + (lane >> 2);
#pragma unroll
        for (int nt = 0; nt < 8; nt++) {
            int gc = col0 + warp_n * 64 + nt * 8 + (lane & 3) * 2;
#pragma unroll
            for (int half = 0; half < 2; half++) {
                int gr = grb + half * 8;
                if (gr >= M || gc >= NCOL) continue;
                epi_store(acc[s][nt][half * 2], acc[s][nt][half * 2 + 1], gr, gc, mode,
                          bias, ls, Cf, ldc, Poh, Pol, P1, s1, rowmap);
            }
        }
    }
}

// single-job kernel
template <int AP>
__global__ __launch_bounds__(256, 2) void mma_gemmT(
    const __half* __restrict__ Ah, const __half* __restrict__ Al, int lda,
    const __half* __restrict__ Bh, const __half* __restrict__ Bl,
    const float* __restrict__ bias,
    float* __restrict__ Cf, int ldc,
    __half* __restrict__ Poh, __half* __restrict__ Pol,
    __half* __restrict__ P1, int s1, const int* __restrict__ rowmap,
    int M, int NCOL, int mode, const float* __restrict__ ls) {
    gemm_body<AP>(Ah, Al, lda, Bh, Bl, bias, Cf, ldc, Poh, Pol, P1, s1, rowmap,
                  M, NCOL, mode, ls);
}

// batched 2-job kernel (blockIdx.z selects job); AP=1 only
struct GemmJob {
    const __half* Ah;
    int lda;
    const __half* Bh;
    const __half* Bl;
    const float* bias;
    float* Cf;
    int ldc;
    __half* P1;
    int s1;
    int M, NCOL;
};

__global__ __launch_bounds__(256, 2) void mma_gemmB(GemmJob j0, GemmJob j1) {
    GemmJob j = (blockIdx.z == 0) ? j0 : j1;
    gemm_body<1>(j.Ah, nullptr, j.lda, j.Bh, j.Bl, j.bias, j.Cf, j.ldc,
                 nullptr, nullptr, j.P1, j.s1, nullptr, j.M, j.NCOL, 0, nullptr);
}

// ------------------------- small utility kernels -------------------------
__global__ void zero_int(int* p, int n) {
    int gid = blockIdx.x * blockDim.x + threadIdx.x;
    if (gid < n) p[gid] = 0;
}

__global__ void hist_kernel(const int* __restrict__ idx, int* __restrict__ cnt, int n) {
    int gid = blockIdx.x * blockDim.x + threadIdx.x;
    if (gid < n) atomicAdd(&cnt[idx[gid]], 1);
}

__global__ void scan1_kernel(const int* __restrict__ in, int* __restrict__ outp1,
                             int* __restrict__ bsums, int n) {
    __shared__ int sh[1024];
    int t = threadIdx.x;
    long base = (long)blockIdx.x * 8192 + (long)t * 8;
    int v[8];
    int run = 0;
#pragma unroll
    for (int i = 0; i < 8; i++) {
        long idx = base + i;
        int x = (idx < n) ? in[idx] : 0;
        run += x;
        v[i] = run;
    }
    sh[t] = run;
    __syncthreads();
    int total = run;
    for (int off = 1; off < 1024; off <<= 1) {
        int y = (t >= off) ? sh[t - off] : 0;
        __syncthreads();
        sh[t] += y;
        __syncthreads();
    }
    int excl = sh[t] - total;
#pragma unroll
    for (int i = 0; i < 8; i++) {
        long idx = base + i;
        if (idx < n) outp1[idx + 1] = v[i] + excl;
    }
    if (t == 1023) bsums[blockIdx.x] = sh[1023];
    if (blockIdx.x == 0 && t == 0) outp1[0] = 0;
}

__global__ void scan2_kernel(int* bsums, int nb) {
    __shared__ int sh[1024];
    int t = threadIdx.x;
    int v = (t < nb) ? bsums[t] : 0;
    sh[t] = v;
    __syncthreads();
    for (int off = 1; off < 1024; off <<= 1) {
        int y = (t >= off) ? sh[t - off] : 0;
        __syncthreads();
        sh[t] += y;
        __syncthreads();
    }
    if (t < nb) bsums[t] = sh[t] - v;  // exclusive
}

__global__ void scan3_kernel(int* outp1, const int* __restrict__ bsums, int n) {
    int gid = blockIdx.x * blockDim.x + threadIdx.x;
    if (gid < n) outp1[gid + 1] += bsums[gid >> 13];
}

__global__ void copy_int(const int* __restrict__ a, int* __restrict__ b, int n) {
    int gid = blockIdx.x * blockDim.x + threadIdx.x;
    if (gid < n) b[gid] = a[gid];
}

__global__ void fill_adj2_kernel(const int* __restrict__ src, const int* __restrict__ dst,
                                 int* __restrict__ fill, int* __restrict__ adjsrc,
                                 int* __restrict__ eperm, int n) {
    int gid = blockIdx.x * blockDim.x + threadIdx.x;
    if (gid < n) {
        int d = dst[gid];
        int pos = atomicAdd(&fill[d], 1);
        adjsrc[pos] = src[gid];
        eperm[gid] = pos;
    }
}

// ------------------------- message passing (no max-shift: |m| is O(1)) -------------------------
__global__ void msg16_kernel(const __half2* __restrict__ h2, const __half2* __restrict__ e2,
                             const int* __restrict__ rowptr, const int* __restrict__ adjsrc,
                             __half* __restrict__ agg) {
    long gid = (long)blockIdx.x * blockDim.x + threadIdx.x;
    if (gid >= (long)NN * 112) return;
    int v = (int)(gid / 112);
    int f = (int)(gid - (long)v * 112);
    int c0 = 2 * f;
    if (c0 >= HD) {
        *(unsigned*)(agg + (long)v * LDP + c0) = 0u;
        return;
    }
    int b = rowptr[v], en = rowptr[v + 1];
    float d0 = 0.f, d1 = 0.f, a0 = 0.f, a1 = 0.f;
    for (int p = b; p < en; p++) {
        int sidx = adjsrc[p];
        float2 hh = __half22float2(h2[(long)sidx * 112 + f]);
        float2 ee = __half22float2(e2[(long)p * 100 + f]);
        float m0 = hh.x + ee.x;
        float m1 = hh.y + ee.y;
        float p0 = __expf(m0);
        float p1 = __expf(m1);
        d0 += p0;
        a0 = fmaf(p0, m0, a0);
        d1 += p1;
        a1 = fmaf(p1, m1, a1);
    }
    float r0 = (d0 > 0.f) ? a0 / d0 : 0.f;
    float r1 = (d1 > 0.f) ? a1 / d1 : 0.f;
    *(__half2*)(agg + (long)v * LDP + c0) = __floats2half2_rn(r0, r1);
}

// ------------------------- graph readout kernels -------------------------
__global__ void gsum_kernel(const __half* __restrict__ hh,
                            const int* __restrict__ gptr, float* __restrict__ g,
                            __half* __restrict__ gp) {
    int gid = blockIdx.x * blockDim.x + threadIdx.x;
    if (gid >= NG * LDP) return;
    int gg = gid / LDP;
    int f = gid - gg * LDP;
    if (f >= HD) {
        gp[gid] = __ushort_as_half(0);
        return;
    }
    int b = gptr[gg], e = gptr[gg + 1];
    float s = 0.f;
    for (int n = b; n < e; n++) s += __half2float(hh[(long)n * LDP + f]);
    g[gg * HD + f] = s;
    gp[gid] = __float2half_rn(s);
}

__global__ void zpre_kernel(const __half* __restrict__ hh,
                            const float* __restrict__ logit_W, float* __restrict__ zh) {
    int warp = (blockIdx.x * blockDim.x + threadIdx.x) >> 5;
    int lane = threadIdx.x & 31;
    if (warp >= NN) return;
    const __half* rh = hh + (long)warp * LDP;
    float s0 = 0.f, s1 = 0.f;
    for (int f = lane; f < HD; f += 32) {
        float hv = __half2float(rh[f]);
        s0 += hv * logit_W[HD + f];
        s1 += hv * logit_W[2 * HD + HD + f];
    }
#pragma unroll
    for (int o = 16; o; o >>= 1) {
        s0 += __shfl_xor_sync(0xffffffffu, s0, o);
        s1 += __shfl_xor_sync(0xffffffffu, s1, o);
    }
    if (lane == 0) {
        zh[warp] = s0;
        zh[NN + warp] = s1;
    }
}

__global__ void zgr_kernel(const float* __restrict__ g, const float* __restrict__ lwg,
                           float* __restrict__ zg) {
    int warp = (blockIdx.x * blockDim.x + threadIdx.x) >> 5;
    int lane = threadIdx.x & 31;
    if (warp >= NG) return;
    const float* grow = g + (long)warp * HD;
    float s = 0.f;
    for (int f = lane; f < HD; f += 32) s += fmaxf(grow[f], 0.f) * lwg[f];
#pragma unroll
    for (int o = 16; o; o >>= 1) s += __shfl_xor_sync(0xffffffffu, s, o);
    if (lane == 0) zg[warp] = s;
}

__global__ void zcomb_kernel(const float* __restrict__ zg, const int* __restrict__ n2g,
                             const float* __restrict__ zh, const float* __restrict__ lb,
                             float* __restrict__ z) {
    int gid = blockIdx.x * blockDim.x + threadIdx.x;
    if (gid >= NN) return;
    float v = zg[n2g[gid]] + zh[gid] + lb[0];
    z[gid] = (v > 0.f) ? v : 0.01f * v;  // leaky_relu
}

__global__ void attn_kernel(const float* __restrict__ z, const int* __restrict__ gptr,
                            float* __restrict__ zmax, float* __restrict__ zden) {
    int warp = (blockIdx.x * blockDim.x + threadIdx.x) >> 5;
    int lane = threadIdx.x & 31;
    if (warp >= NG) return;
    int b = gptr[warp], e = gptr[warp + 1];
    float mx = -3.4e38f;
    for (int i = b + lane; i < e; i += 32) mx = fmaxf(mx, z[i]);
#pragma unroll
    for (int o = 16; o; o >>= 1) mx = fmaxf(mx, __shfl_xor_sync(0xffffffffu, mx, o));
    float s = 0.f;
    for (int i = b + lane; i < e; i += 32) s += __expf(z[i] - mx);
#pragma unroll
    for (int o = 16; o; o >>= 1) s += __shfl_xor_sync(0xffffffffu, s, o);
    if (lane == 0) {
        zmax[warp] = mx;
        zden[warp] = s;
    }
}

__global__ void aw_kernel(const float* __restrict__ z, const int* __restrict__ n2g,
                          const float* __restrict__ zmax, const float* __restrict__ zden,
                          float* __restrict__ aw) {
    int gid = blockIdx.x * blockDim.x + threadIdx.x;
    if (gid >= NN) return;
    int gg = n2g[gid];
    aw[gid] = __expf(z[gid] - zmax[gg]) / zden[gg];
}

__global__ void ctx_kernel(const __half* __restrict__ hv, const float* __restrict__ aw,
                           const int* __restrict__ gptr, __half* __restrict__ ctx) {
    int gid = blockIdx.x * blockDim.x + threadIdx.x;
    if (gid >= NG * LDP) return;
    int gg = gid / LDP;
    int f = gid - gg * LDP;
    if (f >= HD) {
        ctx[gid] = __ushort_as_half(0);
        return;
    }
    int b = gptr[gg], e = gptr[gg + 1];
    float s = 0.f;
    for (int n = b; n < e; n++)
        s = fmaf(__half2float(hv[(long)n * LDP + f]), aw[n], s);
    float v = (s > 0.f) ? s : (__expf(s) - 1.f);  // elu
    ctx[gid] = __float2half_rn(v);
}

__global__ void gru_kernel(const float* __restrict__ gi, const float* __restrict__ gh,
                           float* __restrict__ g, __half* __restrict__ gp) {
    int gid = blockIdx.x * blockDim.x + threadIdx.x;
    if (gid >= NG * HD) return;
    int gg = gid / HD;
    int f = gid - gg * HD;
    const float* gib = gi + gg * 600;
    const float* ghb2 = gh + gg * 600;
    float r = 1.f / (1.f + __expf(-(gib[f] + ghb2[f])));
    float u = 1.f / (1.f + __expf(-(gib[200 + f] + ghb2[200 + f])));
    float nn = tanhf(gib[400 + f] + r * ghb2[400 + f]);
    float v = (1.f - u) * nn + u * g[gid];
    g[gid] = v;
    gp[gg * LDP + f] = __float2half_rn(v);
}

__global__ void out2_kernel(const float* __restrict__ tmp, const float* __restrict__ w2,
                            const float* __restrict__ b2, float* __restrict__ out) {
    int warp = (blockIdx.x * blockDim.x + threadIdx.x) >> 5;
    int lane = threadIdx.x & 31;
    if (warp >= NG) return;
    float s = 0.f;
    const float* row = tmp + (long)warp * 1024;
    for (int c = lane; c < 1024; c += 32) s += fmaxf(row[c], 0.f) * w2[c];
#pragma unroll
    for (int o = 16; o; o >>= 1) s += __shfl_xor_sync(0xffffffffu, s, o);
    if (lane == 0) out[warp] = s + b2[0];
}

// ------------------------- launch -------------------------
static __half *g_pwh, *g_pwl;

static void launch_gemm(int slot, const __half* Ah, const __half* Al, int lda,
                        const float* bias, float* Cf, int ldc,
                        __half* Poh, __half* Pol, __half* P1, int s1,
                        const int* rowmap, int M, int NCOL, int mode, const float* ls) {
    const __half* Bh = g_pwh + (size_t)slot * WSLOT;
    const __half* Bl = g_pwl + (size_t)slot * WSLOT;
    dim3 grid((M + 127) / 128, (NCOL + 127) / 128);
    if (Al)
        mma_gemmT<2><<<grid, 256, 98304>>>(Ah, Al, lda, Bh, Bl, bias, Cf, ldc, Poh, Pol,
                                           P1, s1, rowmap, M, NCOL, mode, ls);
    else
        mma_gemmT<1><<<grid, 256, 73728>>>(Ah, nullptr, lda, Bh, Bl, bias, Cf, ldc, Poh,
                                           Pol, P1, s1, rowmap, M, NCOL, mode, ls);
}

extern "C" void kernel_launch(void* const* d_in, const int* in_sizes, int n_in,
                              void* d_out, int out_size) {
    const float* node_feats = (const float*)d_in[0];
    const float* edge_feats = (const float*)d_in[1];
    const int* src = (const int*)d_in[2];
    const int* dst = (const int*)d_in[3];
    const int* n2g = (const int*)d_in[4];
    const float* atom_W = (const float*)d_in[5];
    const float* atom_b = (const float*)d_in[6];
    const float* bond_W = (const float*)d_in[7];
    const float* bond_b = (const float*)d_in[8];
    const float* mlp_W = (const float*)d_in[9];
    const float* mlp_b = (const float*)d_in[10];
    const float* ls = (const float*)d_in[11];
    const float* logit_W = (const float*)d_in[12];
    const float* logit_b = (const float*)d_in[13];
    const float* proj_W = (const float*)d_in[14];
    const float* proj_b = (const float*)d_in[15];
    const float* gru_Wih = (const float*)d_in[16];
    const float* gru_Whh = (const float*)d_in[17];
    const float* gru_bih = (const float*)d_in[18];
    const float* gru_bhh = (const float*)d_in[19];
    const float* out1_W = (const float*)d_in[20];
    const float* out1_b = (const float*)d_in[21];
    const float* out2_W = (const float*)d_in[22];
    const float* out2_b = (const float*)d_in[23];
    float* out = (float*)d_out;

    cudaFuncSetAttribute(mma_gemmT<2>, cudaFuncAttributeMaxDynamicSharedMemorySize, 98304);
    cudaFuncSetAttribute(mma_gemmT<1>, cudaFuncAttributeMaxDynamicSharedMemorySize, 73728);
    cudaFuncSetAttribute(mma_gemmB, cudaFuncAttributeMaxDynamicSharedMemorySize, 73728);

    __half *phh, *phl, *pagg, *phv, *phv2, *pctx, *pgp, *pnah, *pnal, *pea, *pe16;
    float *pg, *pgi, *pghb, *pt1, *pz, *paw, *pzh, *pzg, *pzmax, *pzden;
    int *pcnt, *prow, *pfill, *pgcnt, *pgptr, *pbs, *padjsrc, *peperm;
    cudaGetSymbolAddress((void**)&phh, d_hh);
    cudaGetSymbolAddress((void**)&phl, d_hl);
    cudaGetSymbolAddress((void**)&pagg, d_agg);
    cudaGetSymbolAddress((void**)&phv, d_hv);
    cudaGetSymbolAddress((void**)&phv2, d_hv2);
    cudaGetSymbolAddress((void**)&pctx, d_ctx);
    cudaGetSymbolAddress((void**)&pgp, d_gp);
    cudaGetSymbolAddress((void**)&pnah, d_nah);
    cudaGetSymbolAddress((void**)&pnal, d_nal);
    cudaGetSymbolAddress((void**)&pea, d_ea);
    cudaGetSymbolAddress((void**)&pe16, d_e16);
    cudaGetSymbolAddress((void**)&pg, d_g);
    cudaGetSymbolAddress((void**)&pgi, d_gi);
    cudaGetSymbolAddress((void**)&pghb, d_ghb);
    cudaGetSymbolAddress((void**)&pt1, d_t1);
    cudaGetSymbolAddress((void**)&pz, d_z);
    cudaGetSymbolAddress((void**)&paw, d_aw);
    cudaGetSymbolAddress((void**)&pzh, d_zh);
    cudaGetSymbolAddress((void**)&pzg, d_zg);
    cudaGetSymbolAddress((void**)&pzmax, d_zmax);
    cudaGetSymbolAddress((void**)&pzden, d_zden);
    cudaGetSymbolAddress((void**)&pcnt, d_cnt);
    cudaGetSymbolAddress((void**)&prow, d_rowptr);
    cudaGetSymbolAddress((void**)&pfill, d_fill);
    cudaGetSymbolAddress((void**)&pgcnt, d_gcnt);
    cudaGetSymbolAddress((void**)&pgptr, d_gptr);
    cudaGetSymbolAddress((void**)&pbs, d_bsums);
    cudaGetSymbolAddress((void**)&padjsrc, d_adjsrc);
    cudaGetSymbolAddress((void**)&peperm, d_eperm);
    cudaGetSymbolAddress((void**)&g_pwh, d_wall_h);
    cudaGetSymbolAddress((void**)&g_pwl, d_wall_l);

    // ---- slot table ----
    WTable T;
    T.s[0] = {atom_W, 74, HD, HD};
    T.s[1] = {bond_W, 12, HD, HD};
    for (int i = 0; i < NLAYERS; i++) T.s[2 + i] = {mlp_W + (size_t)i * HD * HD, HD, HD, HD};
    for (int t = 0; t < TSTEPS; t++) {
        T.s[7 + t] = {proj_W + (size_t)t * HD * HD, HD, HD, HD};
        T.s[9 + t] = {gru_Wih + (size_t)t * HD * 600, HD, 600, 600};
        T.s[11 + t] = {gru_Whh + (size_t)t * HD * 600, HD, 600, 600};
    }
    T.s[13] = {out1_W, HD, 1024, 1024};

    // prep + node encoder early (ncu capture = launch 4)
    wconv_all<<<(NSLOTS * WSLOT + 255) / 256, 256>>>(T, g_pwh, g_pwl);
    split2_kernel<<<(int)(((long)NN * 96 + 255) / 256), 256>>>(node_feats, NN, 74, 96, pnah, pnal);
    split1_kernel<<<(int)(((long)NE * 32 + 255) / 256), 256>>>(edge_feats, NE, 12, 32, pea);
    launch_gemm(0, pnah, pnal, 96, atom_b, nullptr, 0, phh, phl, nullptr, 0, nullptr,
                NN, HD, 0, nullptr);
    zpad_kernel<<<(int)(((long)NN * (LDP - HD) + 255) / 256), 256>>>(phh, phl, NN);

    // ---- CSR by dst ----
    zero_int<<<(NN + 255) / 256, 256>>>(pcnt, NN);
    hist_kernel<<<(NE + 255) / 256, 256>>>(dst, pcnt, NE);
    int nb1 = (NN + 8191) / 8192;
    scan1_kernel<<<nb1, 1024>>>(pcnt, prow, pbs, NN);
    scan2_kernel<<<1, 1024>>>(pbs, nb1);
    scan3_kernel<<<(NN + 255) / 256, 256>>>(prow, pbs, NN);
    copy_int<<<(NN + 255) / 256, 256>>>(prow, pfill, NN);
    fill_adj2_kernel<<<(NE + 255) / 256, 256>>>(src, dst, pfill, padjsrc, peperm, NE);

    // edge encoder: single-plane A, writes e16 directly in CSR order via eperm
    launch_gemm(1, pea, nullptr, 32, bond_b, nullptr, 0, nullptr, nullptr, pe16, HD,
                peperm, NE, HD, 0, nullptr);

    // ---- graph offsets ----
    zero_int<<<(NG + 255) / 256, 256>>>(pgcnt, NG);
    hist_kernel<<<(NN + 255) / 256, 256>>>(n2g, pgcnt, NN);
    scan1_kernel<<<1, 1024>>>(pgcnt, pgptr, pbs, NG);
    scan2_kernel<<<1, 1024>>>(pbs, 1);
    scan3_kernel<<<(NG + 255) / 256, 256>>>(pgptr, pbs, NG);

    // ---- message passing layers ----
    long nthr = (long)NN * 112;
    int mblocks = (int)((nthr + 255) / 256);
    for (int i = 0; i < NLAYERS; i++) {
        msg16_kernel<<<mblocks, 256>>>((const __half2*)phh, (const __half2*)pe16,
                                       prow, padjsrc, pagg);
        launch_gemm(2 + i, pagg, nullptr, LDP, mlp_b + i * HD, nullptr, 0, phh, phl,
                    nullptr, 0, nullptr, NN, HD, 1, ls + i * HD);
    }

    // ---- readout ----
    gsum_kernel<<<(NG * LDP + 255) / 256, 256>>>(phh, pgptr, pg, pgp);
    zpre_kernel<<<(NN * 32 + 255) / 256, 256>>>(phh, logit_W, pzh);

    // batched projections for both t-steps (h is frozen during readout): one pass over h
    {
        GemmJob j0 = {phh, LDP, g_pwh + (size_t)7 * WSLOT, g_pwl + (size_t)7 * WSLOT,
                      proj_b, nullptr, 0, phv, LDP, NN, HD};
        GemmJob j1 = {phh, LDP, g_pwh + (size_t)8 * WSLOT, g_pwl + (size_t)8 * WSLOT,
                      proj_b + HD, nullptr, 0, phv2, LDP, NN, HD};
        dim3 gridP((NN + 127) / 128, (HD + 127) / 128, 2);
        mma_gemmB<<<gridP, 256, 73728>>>(j0, j1);
    }

    for (int t = 0; t < TSTEPS; t++) {
        zgr_kernel<<<(NG * 32 + 255) / 256, 256>>>(pg, logit_W + t * 2 * HD, pzg);
        zcomb_kernel<<<(NN + 255) / 256, 256>>>(pzg, n2g, pzh + t * NN, logit_b + t, pz);
        attn_kernel<<<(NG * 32 + 255) / 256, 256>>>(pz, pgptr, pzmax, pzden);
        aw_kernel<<<(NN + 255) / 256, 256>>>(pz, n2g, pzmax, pzden, paw);
        ctx_kernel<<<(NG * LDP + 255) / 256, 256>>>(t ? phv2 : phv, paw, pgptr, pctx);
        // batched GRU GEMMs: gi = ctx @ Wih, ghb = gp @ Whh (independent)
        {
            GemmJob j0 = {pctx, LDP, g_pwh + (size_t)(9 + t) * WSLOT,
                          g_pwl + (size_t)(9 + t) * WSLOT, gru_bih + t * 600,
                          pgi, 600, nullptr, 0, NG, 600};
            GemmJob j1 = {pgp, LDP, g_pwh + (size_t)(11 + t) * WSLOT,
                          g_pwl + (size_t)(11 + t) * WSLOT, gru_bhh + t * 600,
                          pghb, 600, nullptr, 0, NG, 600};
            dim3 gridG((NG + 127) / 128, (600 + 127) / 128, 2);
            mma_gemmB<<<gridG, 256, 73728>>>(j0, j1);
        }
        gru_kernel<<<(NG * HD + 255) / 256, 256>>>(pgi, pghb, pg, pgp);
    }

    launch_gemm(13, pgp, nullptr, LDP, out1_b, pt1, 1024, nullptr, nullptr, nullptr, 0,
                nullptr, NG, 1024, 0, nullptr);
    out2_kernel<<<(NG * 32 + 255) / 256, 256>>>(pt1, out2_W, out2_b, out);
}